// round 13
// baseline (speedup 1.0000x reference)
#include <cuda_runtime.h>
#include <cuda_fp16.h>
#include <cstdint>

typedef unsigned long long ull;
typedef unsigned uint;

// ---------------------------------------------------------------------------
// Problem constants
// ---------------------------------------------------------------------------
constexpr int B_ = 16, S_ = 2048, D_ = 128;
constexpr int BQ = 128, BK = 128;
constexpr int NIT = S_ / BK;        // 16
constexpr int HSTR = 136;           // halfs per smem row (272B)
constexpr int ROWB = HSTR * 2;      // 272 bytes per padded row

constexpr int PLANE = 128 * ROWB;   // 34816 B per plane
constexpr int QHI = 0;
constexpr int QLO = QHI + PLANE;
constexpr int KHI = QLO + PLANE;    // P_hi overlays after QK
constexpr int KLO = KHI + PLANE;
constexpr int VHI = KLO + PLANE;
constexpr int VLO = VHI + PLANE;
constexpr int REDM = VLO + PLANE;   // float[2][128]
constexpr int REDZ = REDM + 1024;   // float[2][128]
constexpr int MBUF = REDZ + 1024;   // uint[2][512] mask double buffer
constexpr int SMEM_BYTES = MBUF + 4096;   // 215040

constexpr int CHUNKS = PLANE / 16;  // 2176 16B chunks per plane

// Pre-converted K/V planes in global (padded row image identical to smem)
__device__ __align__(256) char gKhi[B_ * S_ * ROWB];
__device__ __align__(256) char gKlo[B_ * S_ * ROWB];
__device__ __align__(256) char gVhi[B_ * S_ * ROWB];
__device__ __align__(256) char gVlo[B_ * S_ * ROWB];

// ---------------------------------------------------------------------------
// Threefry-2x32 (JAX partitionable): key=(0,42), ctr=(0,idx), draw = x0^x1
// ---------------------------------------------------------------------------
__device__ __forceinline__ void tf_round(unsigned &x0, unsigned &x1, int r) {
    x0 += x1;
    x1 = __funnelshift_l(x1, x1, r);
    x1 ^= x0;
}

__device__ __forceinline__ unsigned tf_bits(unsigned idx) {
    const unsigned ks0 = 0u, ks1 = 42u, ks2 = 0x1BD11BDAu ^ 42u;
    unsigned x0 = ks0, x1 = idx + ks1;
    tf_round(x0,x1,13); tf_round(x0,x1,15); tf_round(x0,x1,26); tf_round(x0,x1,6);
    x0 += ks1; x1 += ks2 + 1u;
    tf_round(x0,x1,17); tf_round(x0,x1,29); tf_round(x0,x1,16); tf_round(x0,x1,24);
    x0 += ks2; x1 += ks0 + 2u;
    tf_round(x0,x1,13); tf_round(x0,x1,15); tf_round(x0,x1,26); tf_round(x0,x1,6);
    x0 += ks0; x1 += ks1 + 3u;
    tf_round(x0,x1,17); tf_round(x0,x1,29); tf_round(x0,x1,16); tf_round(x0,x1,24);
    x0 += ks1; x1 += ks2 + 4u;
    tf_round(x0,x1,13); tf_round(x0,x1,15); tf_round(x0,x1,26); tf_round(x0,x1,6);
    x0 += ks2; x1 += ks0 + 5u;
    return x0 ^ x1;
}

// ---------------------------------------------------------------------------
// helpers
// ---------------------------------------------------------------------------
__device__ __forceinline__ float hif(float x) {
    return __half2float(__float2half_rn(x));
}
__device__ __forceinline__ uint packh2(float lo, float hi) {
    uint r; asm("cvt.rn.f16x2.f32 %0, %1, %2;" : "=r"(r) : "f"(hi), "f"(lo)); return r;
}

// ---------------------------------------------------------------------------
// K/V convert kernel (memory-bound, ~20us): fp32 -> fp16 hi/lo padded planes
// ---------------------------------------------------------------------------
__global__ void __launch_bounds__(256) conv_kernel(
    const float* __restrict__ K, const float* __restrict__ V)
{
    const uint u = blockIdx.x * 256u + threadIdx.x;   // 0 .. 2^20-1
    const uint row = u >> 5;
    const uint c4  = (u & 31u) << 2;
    const float4 k4 = *reinterpret_cast<const float4*>(K + (size_t)row * D_ + c4);
    const float4 v4 = *reinterpret_cast<const float4*>(V + (size_t)row * D_ + c4);

    const size_t po = (size_t)row * ROWB + (size_t)c4 * 2;
    {
        const float h0 = hif(k4.x), h1 = hif(k4.y), h2 = hif(k4.z), h3 = hif(k4.w);
        *reinterpret_cast<ull*>(gKhi + po) =
            (ull)packh2(h0, h1) | ((ull)packh2(h2, h3) << 32);
        *reinterpret_cast<ull*>(gKlo + po) =
            (ull)packh2(k4.x - h0, k4.y - h1) | ((ull)packh2(k4.z - h2, k4.w - h3) << 32);
    }
    {
        const float h0 = hif(v4.x), h1 = hif(v4.y), h2 = hif(v4.z), h3 = hif(v4.w);
        *reinterpret_cast<ull*>(gVhi + po) =
            (ull)packh2(h0, h1) | ((ull)packh2(h2, h3) << 32);
        *reinterpret_cast<ull*>(gVlo + po) =
            (ull)packh2(v4.x - h0, v4.y - h1) | ((ull)packh2(v4.z - h2, v4.w - h3) << 32);
    }
}

// ---------------------------------------------------------------------------
// mma / ldmatrix / cp.async / barrier helpers
// ---------------------------------------------------------------------------
__device__ __forceinline__ unsigned smem_u32(const void* p) {
    unsigned a;
    asm("{ .reg .u64 t; cvta.to.shared.u64 t, %1; cvt.u32.u64 %0, t; }"
        : "=r"(a) : "l"(p));
    return a;
}

__device__ __forceinline__ void mma16816(float* c, const uint* a, uint b0, uint b1) {
    asm volatile(
        "mma.sync.aligned.m16n8k16.row.col.f32.f16.f16.f32 "
        "{%0,%1,%2,%3}, {%4,%5,%6,%7}, {%8,%9}, {%0,%1,%2,%3};"
        : "+f"(c[0]), "+f"(c[1]), "+f"(c[2]), "+f"(c[3])
        : "r"(a[0]), "r"(a[1]), "r"(a[2]), "r"(a[3]), "r"(b0), "r"(b1));
}

__device__ __forceinline__ void ldsm4(uint* r, uint addr) {
    asm volatile("ldmatrix.sync.aligned.m8n8.x4.shared.b16 {%0,%1,%2,%3}, [%4];"
        : "=r"(r[0]), "=r"(r[1]), "=r"(r[2]), "=r"(r[3]) : "r"(addr));
}
__device__ __forceinline__ void ldsm4t(uint* r, uint addr) {
    asm volatile("ldmatrix.sync.aligned.m8n8.x4.trans.shared.b16 {%0,%1,%2,%3}, [%4];"
        : "=r"(r[0]), "=r"(r[1]), "=r"(r[2]), "=r"(r[3]) : "r"(addr));
}

__device__ __forceinline__ void cpasync16(uint dst, const void* src) {
    asm volatile("cp.async.cg.shared.global [%0], [%1], 16;" :: "r"(dst), "l"(src));
}
__device__ __forceinline__ void cp_commit() {
    asm volatile("cp.async.commit_group;" ::: "memory");
}
__device__ __forceinline__ void cp_wait1() {
    asm volatile("cp.async.wait_group 1;" ::: "memory");
}
__device__ __forceinline__ void cp_wait0() {
    asm volatile("cp.async.wait_group 0;" ::: "memory");
}

#define BAR_SYNC(id, cnt)   asm volatile("bar.sync %0, %1;"   :: "r"(id), "r"(cnt) : "memory")
#define BAR_ARRIVE(id, cnt) asm volatile("bar.arrive %0, %1;" :: "r"(id), "r"(cnt) : "memory")
// barrier ids: 1,2 = FULL[0],FULL[1]; 3,4 = FREE[0],FREE[1]; 5 = consumer phase sync

__device__ __forceinline__ void split_store(char* smp, int hi_off, int lo_off,
                                            int byte_off, float4 v) {
    const float h0 = hif(v.x), h1 = hif(v.y), h2 = hif(v.z), h3 = hif(v.w);
    const uint hi01 = packh2(h0, h1), hi23 = packh2(h2, h3);
    const uint lo01 = packh2(v.x - h0, v.y - h1), lo23 = packh2(v.z - h2, v.w - h3);
    *reinterpret_cast<ull*>(smp + hi_off + byte_off) = (ull)hi01 | ((ull)hi23 << 32);
    *reinterpret_cast<ull*>(smp + lo_off + byte_off) = (ull)lo01 | ((ull)lo23 << 32);
}

// ---------------------------------------------------------------------------
// Flash attention + warp-specialized Threefry mask producers.
// 640 threads: warps 0-15 = mma consumers (wq = w&7, h = w>>3),
//              warps 16-19 = mask producers (1 per SMSP).
// ---------------------------------------------------------------------------
__global__ void __launch_bounds__(640, 1) attn_kernel(
    const float* __restrict__ Q, const float* __restrict__ inv_scale,
    const float* __restrict__ p_dropout, float* __restrict__ Out)
{
    extern __shared__ char smp[];
    const uint sb = smem_u32(smp);

    const int b     = blockIdx.y;
    const int qbase = blockIdx.x * BQ;
    const int tid   = threadIdx.x;
    const int warp  = tid >> 5;
    const float kp  = 1.0f - *p_dropout;

    if (warp >= 16) {
        // =================== PRODUCER WARPS (mask generation) ===============
        const int pid = tid - 512;                        // 0..127 = local q-row
        const unsigned erow = (unsigned)(b * S_ + qbase + pid) * 2048u;
        for (int kb = 0; kb < NIT; kb++) {
            const int p = kb & 1;
            if (kb >= 2) BAR_SYNC(3 + p, 640);            // buffer free (kb-2 consumed)
            uint* dst = reinterpret_cast<uint*>(smp + MBUF + p * 2048) + pid * 4;
#pragma unroll
            for (int j = 0; j < 4; j++) {
                const unsigned base = erow + (unsigned)(kb * 4 + j) * 32u;
                uint m = 0;
#pragma unroll 8
                for (int e = 0; e < 32; e++) {
                    const unsigned bits = tf_bits(base + (unsigned)e);
                    const float uf = __uint_as_float((bits >> 9) | 0x3f800000u) - 1.0f;
                    m |= (uf < kp ? 1u : 0u) << e;
                }
                dst[j] = m;
            }
            BAR_ARRIVE(1 + p, 640);                       // buffer full
        }
        return;
    }

    // ====================== CONSUMER WARPS (attention) ======================
    const int lane  = tid & 31;
    const int wq    = warp & 7;
    const int h     = warp >> 3;
    const int qr    = wq * 16;
    const int g     = lane >> 2;
    const int tc    = lane & 3;

    const float* Qb = Q + (size_t)(b * S_ + qbase) * D_;
    float* redM = (float*)(smp + REDM);
    float* redZ = (float*)(smp + REDZ);

    // ---- Q -> hi/lo fp16 planes (once) ----
    for (int t = tid; t < 128 * 32; t += 512) {
        const int r = t >> 5, c4 = (t & 31) << 2;
        split_store(smp, QHI, QLO, r * ROWB + c4 * 2,
                    *reinterpret_cast<const float4*>(Qb + r * D_ + c4));
    }

    const float rsc0 = 1.0f / inv_scale[(size_t)b * S_ + qbase + qr + g];
    const float rsc1 = 1.0f / inv_scale[(size_t)b * S_ + qbase + qr + g + 8];

    float oacc[8][4];
#pragma unroll
    for (int nt = 0; nt < 8; nt++)
#pragma unroll
        for (int j = 0; j < 4; j++) oacc[nt][j] = 0.0f;
    float m0 = -1e30f, m1 = -1e30f, z0 = 0.0f, z1 = 0.0f;

    // per-lane ldmatrix byte offsets
    const uint aoff = (uint)((qr + (lane & 15)) * HSTR + ((lane >> 4) << 3)) * 2;
    const uint boff = (uint)(((h * 64 + ((lane >> 4) << 3)) + (lane & 7)) * HSTR
                             + (((lane >> 3) & 1) << 3)) * 2;
    const uint voff = (uint)(((((lane >> 3) & 1) << 3) + (lane & 7)) * HSTR
                             + (h * 64 + ((lane >> 4) << 3))) * 2;

    for (int kb = 0; kb < NIT; kb++) {
        BAR_SYNC(5, 512);   // (a) prior PV reads of P/V done

        // ---- cp.async K planes (group A) then V planes (group B) ----
        {
            const size_t gof = (size_t)(b * S_ + kb * BK) * ROWB;
            for (int i = tid; i < CHUNKS; i += 512) {
                const int o = i * 16;
                cpasync16(sb + KHI + o, gKhi + gof + o);
                cpasync16(sb + KLO + o, gKlo + gof + o);
            }
            cp_commit();
            for (int i = tid; i < CHUNKS; i += 512) {
                const int o = i * 16;
                cpasync16(sb + VHI + o, gVhi + gof + o);
                cpasync16(sb + VLO + o, gVlo + gof + o);
            }
            cp_commit();
        }
        cp_wait1();         // K planes landed
        BAR_SYNC(5, 512);   // (b) K visible

        // ---- S = Q K^T over this warp's 64 keys: sacc[8][4] ----
        float sacc[8][4];
#pragma unroll
        for (int nt = 0; nt < 8; nt++)
#pragma unroll
            for (int j = 0; j < 4; j++) sacc[nt][j] = 0.0f;

#pragma unroll
        for (int ks = 0; ks < 8; ks++) {
            uint ah[4], al[4];
            ldsm4(ah, sb + QHI + aoff + ks * 32);
            ldsm4(al, sb + QLO + aoff + ks * 32);
#pragma unroll
            for (int nt2 = 0; nt2 < 4; nt2++) {
                uint bh[4], bl[4];
                const uint kbo = boff + (uint)(nt2 * 16 * ROWB + ks * 32);
                ldsm4(bh, sb + KHI + kbo);
                ldsm4(bl, sb + KLO + kbo);
                mma16816(sacc[2 * nt2],     ah, bh[0], bh[1]);
                mma16816(sacc[2 * nt2],     al, bh[0], bh[1]);
                mma16816(sacc[2 * nt2],     ah, bl[0], bl[1]);
                mma16816(sacc[2 * nt2 + 1], ah, bh[2], bh[3]);
                mma16816(sacc[2 * nt2 + 1], al, bh[2], bh[3]);
                mma16816(sacc[2 * nt2 + 1], ah, bl[2], bl[3]);
            }
        }

        // ---- scale + half-local max ----
        float mx0 = -1e30f, mx1 = -1e30f;
#pragma unroll
        for (int nt = 0; nt < 8; nt++) {
            sacc[nt][0] *= rsc0; sacc[nt][1] *= rsc0;
            sacc[nt][2] *= rsc1; sacc[nt][3] *= rsc1;
            mx0 = fmaxf(mx0, fmaxf(sacc[nt][0], sacc[nt][1]));
            mx1 = fmaxf(mx1, fmaxf(sacc[nt][2], sacc[nt][3]));
        }
        mx0 = fmaxf(mx0, __shfl_xor_sync(0xffffffffu, mx0, 1));
        mx0 = fmaxf(mx0, __shfl_xor_sync(0xffffffffu, mx0, 2));
        mx1 = fmaxf(mx1, __shfl_xor_sync(0xffffffffu, mx1, 1));
        mx1 = fmaxf(mx1, __shfl_xor_sync(0xffffffffu, mx1, 2));

        if (tc == 0) {
            redM[h * 128 + qr + g]     = mx0;
            redM[h * 128 + qr + g + 8] = mx1;
        }
        BAR_SYNC(5, 512);   // (c) max exchange; all QK reads of K done
        mx0 = fmaxf(mx0, redM[(1 - h) * 128 + qr + g]);
        mx1 = fmaxf(mx1, redM[(1 - h) * 128 + qr + g + 8]);

        const float mn0 = fmaxf(m0, mx0), mn1 = fmaxf(m1, mx1);
        const float al0 = __expf(m0 - mn0), al1 = __expf(m1 - mn1);
        m0 = mn0; m1 = mn1;

        // ---- exp + Z partial (reduced across 4-lane group here ONLY) ----
        float zp0 = 0.0f, zp1 = 0.0f;
#pragma unroll
        for (int nt = 0; nt < 8; nt++) {
            sacc[nt][0] = __expf(sacc[nt][0] - mn0); zp0 += sacc[nt][0];
            sacc[nt][1] = __expf(sacc[nt][1] - mn0); zp0 += sacc[nt][1];
            sacc[nt][2] = __expf(sacc[nt][2] - mn1); zp1 += sacc[nt][2];
            sacc[nt][3] = __expf(sacc[nt][3] - mn1); zp1 += sacc[nt][3];
        }
        zp0 += __shfl_xor_sync(0xffffffffu, zp0, 1);
        zp0 += __shfl_xor_sync(0xffffffffu, zp0, 2);
        zp1 += __shfl_xor_sync(0xffffffffu, zp1, 1);
        zp1 += __shfl_xor_sync(0xffffffffu, zp1, 2);
        z0 = z0 * al0 + zp0;
        z1 = z1 * al1 + zp1;

        // ---- dropout from producer-generated smem mask ----
        {
            const int p = kb & 1;
            BAR_SYNC(1 + p, 640);   // wait producers: buffer full
            const uint* mb = reinterpret_cast<const uint*>(smp + MBUF + p * 2048);
            const uint w00 = mb[(qr + g) * 4 + h * 2];
            const uint w01 = mb[(qr + g) * 4 + h * 2 + 1];
            const uint w10 = mb[(qr + g + 8) * 4 + h * 2];
            const uint w11 = mb[(qr + g + 8) * 4 + h * 2 + 1];
            BAR_ARRIVE(3 + p, 640); // buffer free
#pragma unroll
            for (int nt = 0; nt < 8; nt++) {
                const uint bit = (uint)((nt & 3) * 8 + tc * 2);
                const uint ww0 = (nt >> 2) ? w01 : w00;
                const uint ww1 = (nt >> 2) ? w11 : w10;
                if (!((ww0 >> bit) & 1u))        sacc[nt][0] = 0.0f;
                if (!((ww0 >> (bit + 1)) & 1u))  sacc[nt][1] = 0.0f;
                if (!((ww1 >> bit) & 1u))        sacc[nt][2] = 0.0f;
                if (!((ww1 >> (bit + 1)) & 1u))  sacc[nt][3] = 0.0f;
            }
        }

        // ---- write P_hi into KHI plane; rescale O partial ----
#pragma unroll
        for (int nt = 0; nt < 8; nt++) {
            const int keyc = h * 64 + (nt >> 1) * 16 + (nt & 1) * 8 + tc * 2;
            *(uint*)(smp + KHI + (qr + g) * ROWB + keyc * 2) =
                packh2(sacc[nt][0], sacc[nt][1]);
            *(uint*)(smp + KHI + (qr + g + 8) * ROWB + keyc * 2) =
                packh2(sacc[nt][2], sacc[nt][3]);
        }
#pragma unroll
        for (int nt = 0; nt < 8; nt++) {
            oacc[nt][0] *= al0; oacc[nt][1] *= al0;
            oacc[nt][2] *= al1; oacc[nt][3] *= al1;
        }
        cp_wait0();         // V planes landed
        BAR_SYNC(5, 512);   // (d) P + V ready

        // ---- O += P_hi * (V_hi + V_lo), all 128 keys, this warp's 64 d-cols ----
#pragma unroll
        for (int ks = 0; ks < 8; ks++) {
            uint ph[4];
            ldsm4(ph, sb + KHI + aoff + ks * 32);
#pragma unroll
            for (int dt2 = 0; dt2 < 4; dt2++) {
                uint vh[4], vl[4];
                const uint vbo = voff + (uint)(ks * 16 * ROWB + dt2 * 32);
                ldsm4t(vh, sb + VHI + vbo);
                ldsm4t(vl, sb + VLO + vbo);
                mma16816(oacc[2 * dt2],     ph, vh[0], vh[1]);
                mma16816(oacc[2 * dt2],     ph, vl[0], vl[1]);
                mma16816(oacc[2 * dt2 + 1], ph, vh[2], vh[3]);
                mma16816(oacc[2 * dt2 + 1], ph, vl[2], vl[3]);
            }
        }
    }

    // ---- epilogue: z0/z1 already lane-group-reduced; exchange halves only ----
    if (tc == 0) {
        redZ[h * 128 + qr + g]     = z0;
        redZ[h * 128 + qr + g + 8] = z1;
    }
    BAR_SYNC(5, 512);
    const float Z0 = redZ[qr + g]     + redZ[128 + qr + g];
    const float Z1 = redZ[qr + g + 8] + redZ[128 + qr + g + 8];
    const float inv0 = 1.0f / (Z0 * kp);
    const float inv1 = 1.0f / (Z1 * kp);

    float* o0 = Out + (size_t)(b * S_ + qbase + qr + g) * D_ + h * 64 + tc * 2;
    float* o1 = Out + (size_t)(b * S_ + qbase + qr + g + 8) * D_ + h * 64 + tc * 2;
#pragma unroll
    for (int nt = 0; nt < 8; nt++) {
        const int dcol = (nt >> 1) * 16 + (nt & 1) * 8;
        *reinterpret_cast<float2*>(o0 + dcol) =
            make_float2(oacc[nt][0] * inv0, oacc[nt][1] * inv0);
        *reinterpret_cast<float2*>(o1 + dcol) =
            make_float2(oacc[nt][2] * inv1, oacc[nt][3] * inv1);
    }
}

// ---------------------------------------------------------------------------
// Launch
// ---------------------------------------------------------------------------
extern "C" void kernel_launch(void* const* d_in, const int* in_sizes, int n_in,
                              void* d_out, int out_size) {
    const float* Q   = (const float*)d_in[0];
    const float* K   = (const float*)d_in[1];
    const float* V   = (const float*)d_in[2];
    const float* isf = (const float*)d_in[3];
    const float* dp  = (const float*)d_in[4];
    float* Out = (float*)d_out;

    cudaFuncSetAttribute(attn_kernel,
                         cudaFuncAttributeMaxDynamicSharedMemorySize, SMEM_BYTES);

    // 1) K/V fp32 -> fp16 hi/lo plane conversion (memory-bound, ~20us)
    conv_kernel<<<(1u << 20) / 256, 256>>>(K, V);

    // 2) flash attention with in-kernel warp-specialized mask producers
    dim3 grid(S_ / BQ, B_);
    attn_kernel<<<grid, 640, SMEM_BYTES>>>(Q, isf, dp, Out);
}

// round 14
// speedup vs baseline: 1.3952x; 1.3952x over previous
#include <cuda_runtime.h>
#include <cuda_fp16.h>
#include <cstdint>

typedef unsigned long long ull;
typedef unsigned uint;

// ---------------------------------------------------------------------------
// Problem constants
// ---------------------------------------------------------------------------
constexpr int B_ = 16, S_ = 2048, D_ = 128;
constexpr int BQ = 128, BK = 128;
constexpr int NIT = S_ / BK;        // 16
constexpr int HSTR = 136;           // halfs per smem row (272B, conflict-free ldmatrix)
constexpr int ROWB = HSTR * 2;      // 272 bytes per padded row

constexpr int PLANE = 128 * ROWB;   // 34816 B per 128-row plane
constexpr int QHI = 0;
constexpr int QLO = QHI + PLANE;
constexpr int KHI = QLO + PLANE;    // P_hi overlays after QK
constexpr int KLO = KHI + PLANE;
constexpr int VHI = KLO + PLANE;
constexpr int VLO = VHI + PLANE;
constexpr int REDM = VLO + PLANE;   // float[2][128]
constexpr int REDZ = REDM + 1024;   // float[2][128]
constexpr int SMEM_BYTES = REDZ + 1024;   // 210944

constexpr int CHUNKS = PLANE / 16;  // 2176 16B chunks per plane

// Pre-converted K/V planes in global (padded row image identical to smem)
__device__ __align__(256) char gKhi[B_ * S_ * ROWB];
__device__ __align__(256) char gKlo[B_ * S_ * ROWB];
__device__ __align__(256) char gVhi[B_ * S_ * ROWB];
__device__ __align__(256) char gVlo[B_ * S_ * ROWB];

// Packed dropout keep-mask: 16*2048*2048 bits = 8 MB
__device__ __align__(16) uint g_mask[(1u << 26) / 32];

// ---------------------------------------------------------------------------
// Threefry-2x32 (JAX partitionable): key=(0,42), ctr=(0,idx), draw = x0^x1
// ---------------------------------------------------------------------------
__device__ __forceinline__ void tf_round(unsigned &x0, unsigned &x1, int r) {
    x0 += x1;
    x1 = __funnelshift_l(x1, x1, r);
    x1 ^= x0;
}

__device__ __forceinline__ unsigned tf_bits(unsigned idx) {
    const unsigned ks0 = 0u, ks1 = 42u, ks2 = 0x1BD11BDAu ^ 42u;
    unsigned x0 = ks0, x1 = idx + ks1;
    tf_round(x0,x1,13); tf_round(x0,x1,15); tf_round(x0,x1,26); tf_round(x0,x1,6);
    x0 += ks1; x1 += ks2 + 1u;
    tf_round(x0,x1,17); tf_round(x0,x1,29); tf_round(x0,x1,16); tf_round(x0,x1,24);
    x0 += ks2; x1 += ks0 + 2u;
    tf_round(x0,x1,13); tf_round(x0,x1,15); tf_round(x0,x1,26); tf_round(x0,x1,6);
    x0 += ks0; x1 += ks1 + 3u;
    tf_round(x0,x1,17); tf_round(x0,x1,29); tf_round(x0,x1,16); tf_round(x0,x1,24);
    x0 += ks1; x1 += ks2 + 4u;
    tf_round(x0,x1,13); tf_round(x0,x1,15); tf_round(x0,x1,26); tf_round(x0,x1,6);
    x0 += ks2; x1 += ks0 + 5u;
    return x0 ^ x1;
}

// ---------------------------------------------------------------------------
// helpers
// ---------------------------------------------------------------------------
__device__ __forceinline__ float hif(float x) {
    return __half2float(__float2half_rn(x));
}
__device__ __forceinline__ uint packh2(float lo, float hi) {
    uint r; asm("cvt.rn.f16x2.f32 %0, %1, %2;" : "=r"(r) : "f"(hi), "f"(lo)); return r;
}

// ---------------------------------------------------------------------------
// Fused mask + K/V convert kernel. 8192 blocks x 256 threads = 2^21 threads.
// Every thread: 1 mask word (32 threefry chains, ALU-bound).
// Threads u < 2^20 additionally convert one float4 of K and V to fp16 hi/lo
// planes (memory-bound; hides under the block's ALU work).
// ---------------------------------------------------------------------------
__global__ void __launch_bounds__(256) maskconv_kernel(
    const float* __restrict__ K, const float* __restrict__ V,
    const float* __restrict__ p_dropout)
{
    const uint u = blockIdx.x * 256u + threadIdx.x;   // 0 .. 2^21-1
    const float kp = 1.0f - *p_dropout;

    // ---- convert (only first 2^20 threads: 32768 rows x 32 float4) ----
    if (u < (1u << 20)) {
        const uint row = u >> 5;
        const uint c4  = (u & 31u) << 2;
        const float4 k4 = *reinterpret_cast<const float4*>(K + (size_t)row * D_ + c4);
        const float4 v4 = *reinterpret_cast<const float4*>(V + (size_t)row * D_ + c4);

        const size_t po = (size_t)row * ROWB + (size_t)c4 * 2;
        {
            const float h0 = hif(k4.x), h1 = hif(k4.y), h2 = hif(k4.z), h3 = hif(k4.w);
            *reinterpret_cast<ull*>(gKhi + po) =
                (ull)packh2(h0, h1) | ((ull)packh2(h2, h3) << 32);
            *reinterpret_cast<ull*>(gKlo + po) =
                (ull)packh2(k4.x - h0, k4.y - h1) | ((ull)packh2(k4.z - h2, k4.w - h3) << 32);
        }
        {
            const float h0 = hif(v4.x), h1 = hif(v4.y), h2 = hif(v4.z), h3 = hif(v4.w);
            *reinterpret_cast<ull*>(gVhi + po) =
                (ull)packh2(h0, h1) | ((ull)packh2(h2, h3) << 32);
            *reinterpret_cast<ull*>(gVlo + po) =
                (ull)packh2(v4.x - h0, v4.y - h1) | ((ull)packh2(v4.z - h2, v4.w - h3) << 32);
        }
    }

    // ---- mask: this thread builds word u (elements 32u .. 32u+31) ----
    const unsigned ebase = u << 5;
    uint m = 0;
#pragma unroll 8
    for (int e = 0; e < 32; e++) {
        const unsigned bits = tf_bits(ebase + (unsigned)e);
        const float uf = __uint_as_float((bits >> 9) | 0x3f800000u) - 1.0f;
        m |= (uf < kp ? 1u : 0u) << e;
    }
    g_mask[u] = m;
}

// ---------------------------------------------------------------------------
// mma / ldmatrix / cp.async helpers (baseline PTX)
// ---------------------------------------------------------------------------
__device__ __forceinline__ unsigned smem_u32(const void* p) {
    unsigned a;
    asm("{ .reg .u64 t; cvta.to.shared.u64 t, %1; cvt.u32.u64 %0, t; }"
        : "=r"(a) : "l"(p));
    return a;
}

__device__ __forceinline__ void mma16816(float* c, const uint* a, uint b0, uint b1) {
    asm volatile(
        "mma.sync.aligned.m16n8k16.row.col.f32.f16.f16.f32 "
        "{%0,%1,%2,%3}, {%4,%5,%6,%7}, {%8,%9}, {%0,%1,%2,%3};"
        : "+f"(c[0]), "+f"(c[1]), "+f"(c[2]), "+f"(c[3])
        : "r"(a[0]), "r"(a[1]), "r"(a[2]), "r"(a[3]), "r"(b0), "r"(b1));
}

__device__ __forceinline__ void ldsm4(uint* r, uint addr) {
    asm volatile("ldmatrix.sync.aligned.m8n8.x4.shared.b16 {%0,%1,%2,%3}, [%4];"
        : "=r"(r[0]), "=r"(r[1]), "=r"(r[2]), "=r"(r[3]) : "r"(addr));
}
__device__ __forceinline__ void ldsm4t(uint* r, uint addr) {
    asm volatile("ldmatrix.sync.aligned.m8n8.x4.trans.shared.b16 {%0,%1,%2,%3}, [%4];"
        : "=r"(r[0]), "=r"(r[1]), "=r"(r[2]), "=r"(r[3]) : "r"(addr));
}

__device__ __forceinline__ void cpasync16(uint dst, const void* src) {
    asm volatile("cp.async.cg.shared.global [%0], [%1], 16;" :: "r"(dst), "l"(src));
}
__device__ __forceinline__ void cp_commit() {
    asm volatile("cp.async.commit_group;" ::: "memory");
}
__device__ __forceinline__ void cp_wait1() {
    asm volatile("cp.async.wait_group 1;" ::: "memory");
}
__device__ __forceinline__ void cp_wait0() {
    asm volatile("cp.async.wait_group 0;" ::: "memory");
}

__device__ __forceinline__ void split_store(char* smp, int hi_off, int lo_off,
                                            int byte_off, float4 v) {
    const float h0 = hif(v.x), h1 = hif(v.y), h2 = hif(v.z), h3 = hif(v.w);
    const uint hi01 = packh2(h0, h1), hi23 = packh2(h2, h3);
    const uint lo01 = packh2(v.x - h0, v.y - h1), lo23 = packh2(v.z - h2, v.w - h3);
    *reinterpret_cast<ull*>(smp + hi_off + byte_off) = (ull)hi01 | ((ull)hi23 << 32);
    *reinterpret_cast<ull*>(smp + lo_off + byte_off) = (ull)lo01 | ((ull)lo23 << 32);
}

// ---------------------------------------------------------------------------
// Flash attention: split-fp16 HMMA, BQ=BK=128, 512 threads (16 warps).
// warp w: wq = w&7 -> q-rows 16*wq;  h = w>>3 -> key-half (QK) / d-half (PV).
// K/V tiles arrive via cp.async from pre-converted global planes.
// PV uses 2-term split (P_hi x V_hi + P_hi x V_lo); QK stays 3-term.
// ---------------------------------------------------------------------------
__global__ void __launch_bounds__(512, 1) attn_kernel(
    const float* __restrict__ Q, const float* __restrict__ inv_scale,
    const float* __restrict__ p_dropout, float* __restrict__ Out)
{
    extern __shared__ char smp[];
    const uint sb = smem_u32(smp);

    const int b     = blockIdx.y;
    const int qbase = blockIdx.x * BQ;
    const int tid   = threadIdx.x;
    const int lane  = tid & 31;
    const int warp  = tid >> 5;
    const int wq    = warp & 7;
    const int h     = warp >> 3;
    const int qr    = wq * 16;
    const int g     = lane >> 2;
    const int tc    = lane & 3;

    const float kp = 1.0f - *p_dropout;
    const float* Qb = Q + (size_t)(b * S_ + qbase) * D_;

    float* redM = (float*)(smp + REDM);
    float* redZ = (float*)(smp + REDZ);

    // ---- Q -> hi/lo fp16 planes (once) ----
    for (int t = tid; t < 128 * 32; t += 512) {
        const int r = t >> 5, c4 = (t & 31) << 2;
        split_store(smp, QHI, QLO, r * ROWB + c4 * 2,
                    *reinterpret_cast<const float4*>(Qb + r * D_ + c4));
    }

    const float rsc0 = 1.0f / inv_scale[(size_t)b * S_ + qbase + qr + g];
    const float rsc1 = 1.0f / inv_scale[(size_t)b * S_ + qbase + qr + g + 8];

    float oacc[8][4];
#pragma unroll
    for (int nt = 0; nt < 8; nt++)
#pragma unroll
        for (int j = 0; j < 4; j++) oacc[nt][j] = 0.0f;
    float m0 = -1e30f, m1 = -1e30f, z0 = 0.0f, z1 = 0.0f;

    const unsigned rowb0 = (unsigned)(b * S_ + qbase + qr + g) * 64u;
    const unsigned rowb1 = rowb0 + 512u;

    // per-lane ldmatrix byte offsets
    const uint aoff = (uint)((qr + (lane & 15)) * HSTR + ((lane >> 4) << 3)) * 2;
    const uint boff = (uint)(((h * 64 + ((lane >> 4) << 3)) + (lane & 7)) * HSTR
                             + (((lane >> 3) & 1) << 3)) * 2;
    const uint voff = (uint)(((((lane >> 3) & 1) << 3) + (lane & 7)) * HSTR
                             + (h * 64 + ((lane >> 4) << 3))) * 2;

    for (int kb = 0; kb < NIT; kb++) {
        __syncthreads();   // (a) prior PV reads of P/V done

        // ---- cp.async K planes (group A) then V planes (group B) ----
        {
            const size_t gof = (size_t)(b * S_ + kb * BK) * ROWB;
            for (int i = tid; i < CHUNKS; i += 512) {
                const int o = i * 16;
                cpasync16(sb + KHI + o, gKhi + gof + o);
                cpasync16(sb + KLO + o, gKlo + gof + o);
            }
            cp_commit();
            for (int i = tid; i < CHUNKS; i += 512) {
                const int o = i * 16;
                cpasync16(sb + VHI + o, gVhi + gof + o);
                cpasync16(sb + VLO + o, gVlo + gof + o);
            }
            cp_commit();
        }
        cp_wait1();        // K planes landed (V still in flight)
        __syncthreads();   // (b) K visible to all warps

        // ---- S = Q K^T over this warp's 64 keys: sacc[8][4] (3-term) ----
        float sacc[8][4];
#pragma unroll
        for (int nt = 0; nt < 8; nt++)
#pragma unroll
            for (int j = 0; j < 4; j++) sacc[nt][j] = 0.0f;

#pragma unroll
        for (int ks = 0; ks < 8; ks++) {
            uint ah[4], al[4];
            ldsm4(ah, sb + QHI + aoff + ks * 32);
            ldsm4(al, sb + QLO + aoff + ks * 32);
#pragma unroll
            for (int nt2 = 0; nt2 < 4; nt2++) {
                uint bh[4], bl[4];
                const uint kbo = boff + (uint)(nt2 * 16 * ROWB + ks * 32);
                ldsm4(bh, sb + KHI + kbo);
                ldsm4(bl, sb + KLO + kbo);
                mma16816(sacc[2 * nt2],     ah, bh[0], bh[1]);
                mma16816(sacc[2 * nt2],     al, bh[0], bh[1]);
                mma16816(sacc[2 * nt2],     ah, bl[0], bl[1]);
                mma16816(sacc[2 * nt2 + 1], ah, bh[2], bh[3]);
                mma16816(sacc[2 * nt2 + 1], al, bh[2], bh[3]);
                mma16816(sacc[2 * nt2 + 1], ah, bl[2], bl[3]);
            }
        }

        // ---- scale + half-local max ----
        float mx0 = -1e30f, mx1 = -1e30f;
#pragma unroll
        for (int nt = 0; nt < 8; nt++) {
            sacc[nt][0] *= rsc0; sacc[nt][1] *= rsc0;
            sacc[nt][2] *= rsc1; sacc[nt][3] *= rsc1;
            mx0 = fmaxf(mx0, fmaxf(sacc[nt][0], sacc[nt][1]));
            mx1 = fmaxf(mx1, fmaxf(sacc[nt][2], sacc[nt][3]));
        }
        mx0 = fmaxf(mx0, __shfl_xor_sync(0xffffffffu, mx0, 1));
        mx0 = fmaxf(mx0, __shfl_xor_sync(0xffffffffu, mx0, 2));
        mx1 = fmaxf(mx1, __shfl_xor_sync(0xffffffffu, mx1, 1));
        mx1 = fmaxf(mx1, __shfl_xor_sync(0xffffffffu, mx1, 2));

        if (tc == 0) {
            redM[h * 128 + qr + g]     = mx0;
            redM[h * 128 + qr + g + 8] = mx1;
        }
        __syncthreads();   // (c) max exchange; all QK reads of K done
        mx0 = fmaxf(mx0, redM[(1 - h) * 128 + qr + g]);
        mx1 = fmaxf(mx1, redM[(1 - h) * 128 + qr + g + 8]);

        const float mn0 = fmaxf(m0, mx0), mn1 = fmaxf(m1, mx1);
        const float al0 = __expf(m0 - mn0), al1 = __expf(m1 - mn1);
        m0 = mn0; m1 = mn1;

        // ---- exp + Z partial ----
        float zp0 = 0.0f, zp1 = 0.0f;
#pragma unroll
        for (int nt = 0; nt < 8; nt++) {
            sacc[nt][0] = __expf(sacc[nt][0] - mn0); zp0 += sacc[nt][0];
            sacc[nt][1] = __expf(sacc[nt][1] - mn0); zp0 += sacc[nt][1];
            sacc[nt][2] = __expf(sacc[nt][2] - mn1); zp1 += sacc[nt][2];
            sacc[nt][3] = __expf(sacc[nt][3] - mn1); zp1 += sacc[nt][3];
        }
        zp0 += __shfl_xor_sync(0xffffffffu, zp0, 1);
        zp0 += __shfl_xor_sync(0xffffffffu, zp0, 2);
        zp1 += __shfl_xor_sync(0xffffffffu, zp1, 1);
        zp1 += __shfl_xor_sync(0xffffffffu, zp1, 2);
        z0 = z0 * al0 + zp0;
        z1 = z1 * al1 + zp1;

        // ---- dropout from precomputed mask ----
        uint w0[2], w1[2];
#pragma unroll
        for (int j = 0; j < 2; j++) {
            w0[j] = g_mask[rowb0 + (unsigned)(kb * 4 + h * 2 + j)];
            w1[j] = g_mask[rowb1 + (unsigned)(kb * 4 + h * 2 + j)];
        }
#pragma unroll
        for (int nt = 0; nt < 8; nt++) {
            const uint bit = (uint)((nt & 3) * 8 + tc * 2);
            const uint ww0 = w0[nt >> 2], ww1 = w1[nt >> 2];
            if (!((ww0 >> bit) & 1u))        sacc[nt][0] = 0.0f;
            if (!((ww0 >> (bit + 1)) & 1u))  sacc[nt][1] = 0.0f;
            if (!((ww1 >> bit) & 1u))        sacc[nt][2] = 0.0f;
            if (!((ww1 >> (bit + 1)) & 1u))  sacc[nt][3] = 0.0f;
        }

        // ---- write P_hi into KHI plane; rescale O partial ----
#pragma unroll
        for (int nt = 0; nt < 8; nt++) {
            const int keyc = h * 64 + (nt >> 1) * 16 + (nt & 1) * 8 + tc * 2;
            *(uint*)(smp + KHI + (qr + g) * ROWB + keyc * 2) =
                packh2(sacc[nt][0], sacc[nt][1]);
            *(uint*)(smp + KHI + (qr + g + 8) * ROWB + keyc * 2) =
                packh2(sacc[nt][2], sacc[nt][3]);
        }
#pragma unroll
        for (int nt = 0; nt < 8; nt++) {
            oacc[nt][0] *= al0; oacc[nt][1] *= al0;
            oacc[nt][2] *= al1; oacc[nt][3] *= al1;
        }
        cp_wait0();        // V planes landed
        __syncthreads();   // (d) P + V ready

        // ---- O += P_hi * (V_hi + V_lo), all 128 keys, this warp's 64 d-cols ----
#pragma unroll
        for (int ks = 0; ks < 8; ks++) {
            uint ph[4];
            ldsm4(ph, sb + KHI + aoff + ks * 32);
#pragma unroll
            for (int dt2 = 0; dt2 < 4; dt2++) {
                uint vh[4], vl[4];
                const uint vbo = voff + (uint)(ks * 16 * ROWB + dt2 * 32);
                ldsm4t(vh, sb + VHI + vbo);
                ldsm4t(vl, sb + VLO + vbo);
                mma16816(oacc[2 * dt2],     ph, vh[0], vh[1]);
                mma16816(oacc[2 * dt2],     ph, vl[0], vl[1]);
                mma16816(oacc[2 * dt2 + 1], ph, vh[2], vh[3]);
                mma16816(oacc[2 * dt2 + 1], ph, vl[2], vl[3]);
            }
        }
    }

    // ---- epilogue: exchange Z halves, normalize, store ----
    if (tc == 0) {
        redZ[h * 128 + qr + g]     = z0;
        redZ[h * 128 + qr + g + 8] = z1;
    }
    __syncthreads();
    const float Z0 = redZ[qr + g]     + redZ[128 + qr + g];
    const float Z1 = redZ[qr + g + 8] + redZ[128 + qr + g + 8];
    const float inv0 = 1.0f / (Z0 * kp);
    const float inv1 = 1.0f / (Z1 * kp);

    float* o0 = Out + (size_t)(b * S_ + qbase + qr + g) * D_ + h * 64 + tc * 2;
    float* o1 = Out + (size_t)(b * S_ + qbase + qr + g + 8) * D_ + h * 64 + tc * 2;
#pragma unroll
    for (int nt = 0; nt < 8; nt++) {
        const int dcol = (nt >> 1) * 16 + (nt & 1) * 8;
        *reinterpret_cast<float2*>(o0 + dcol) =
            make_float2(oacc[nt][0] * inv0, oacc[nt][1] * inv0);
        *reinterpret_cast<float2*>(o1 + dcol) =
            make_float2(oacc[nt][2] * inv1, oacc[nt][3] * inv1);
    }
}

// ---------------------------------------------------------------------------
// Launch
// ---------------------------------------------------------------------------
extern "C" void kernel_launch(void* const* d_in, const int* in_sizes, int n_in,
                              void* d_out, int out_size) {
    const float* Q   = (const float*)d_in[0];
    const float* K   = (const float*)d_in[1];
    const float* V   = (const float*)d_in[2];
    const float* isf = (const float*)d_in[3];
    const float* dp  = (const float*)d_in[4];
    float* Out = (float*)d_out;

    cudaFuncSetAttribute(attn_kernel,
                         cudaFuncAttributeMaxDynamicSharedMemorySize, SMEM_BYTES);

    // 1) fused: dropout mask (ALU-bound) + K/V fp16 hi/lo conversion (mem-bound)
    maskconv_kernel<<<(1u << 21) / 256, 256>>>(K, V, dp);

    // 2) flash attention (cp.async from pre-converted planes, 2-term PV)
    dim3 grid(S_ / BQ, B_);
    attn_kernel<<<grid, 512, SMEM_BYTES>>>(Q, isf, dp, Out);
}

// round 15
// speedup vs baseline: 1.4166x; 1.0153x over previous
#include <cuda_runtime.h>
#include <cuda_fp16.h>
#include <cstdint>

typedef unsigned long long ull;
typedef unsigned uint;

// ---------------------------------------------------------------------------
// Problem constants
// ---------------------------------------------------------------------------
constexpr int B_ = 16, S_ = 2048, D_ = 128;
constexpr int BQ = 128, BK = 128;
constexpr int NIT = S_ / BK;        // 16
constexpr int HSTR = 136;           // halfs per smem row (272B)
constexpr int ROWB = HSTR * 2;      // 272 bytes per padded row

constexpr int PLANE = 128 * ROWB;   // 34816 B per 128-row plane
constexpr int QHI = 0;
constexpr int QLO = QHI + PLANE;
constexpr int KHI = QLO + PLANE;    // P_hi overlays after QK
constexpr int KLO = KHI + PLANE;
constexpr int VHI = KLO + PLANE;
constexpr int VLO = VHI + PLANE;
constexpr int REDM = VLO + PLANE;   // float[2][128]
constexpr int REDZ = REDM + 1024;   // float[2][128]
constexpr int SMEM_BYTES = REDZ + 1024;   // 210944

constexpr int CHUNKS = PLANE / 16;  // 2176 16B chunks per plane

// Pre-converted K/V planes in global (padded row image identical to smem)
__device__ __align__(256) char gKhi[B_ * S_ * ROWB];
__device__ __align__(256) char gKlo[B_ * S_ * ROWB];
__device__ __align__(256) char gVhi[B_ * S_ * ROWB];
__device__ __align__(256) char gVlo[B_ * S_ * ROWB];

// ---------------------------------------------------------------------------
// Threefry-2x32 (JAX partitionable): key=(0,42), ctr=(0,idx), draw = x0^x1
// ---------------------------------------------------------------------------
__device__ __forceinline__ void tf_round(unsigned &x0, unsigned &x1, int r) {
    x0 += x1;
    x1 = __funnelshift_l(x1, x1, r);
    x1 ^= x0;
}

__device__ __forceinline__ unsigned tf_bits(unsigned idx) {
    const unsigned ks0 = 0u, ks1 = 42u, ks2 = 0x1BD11BDAu ^ 42u;
    unsigned x0 = ks0, x1 = idx + ks1;
    tf_round(x0,x1,13); tf_round(x0,x1,15); tf_round(x0,x1,26); tf_round(x0,x1,6);
    x0 += ks1; x1 += ks2 + 1u;
    tf_round(x0,x1,17); tf_round(x0,x1,29); tf_round(x0,x1,16); tf_round(x0,x1,24);
    x0 += ks2; x1 += ks0 + 2u;
    tf_round(x0,x1,13); tf_round(x0,x1,15); tf_round(x0,x1,26); tf_round(x0,x1,6);
    x0 += ks0; x1 += ks1 + 3u;
    tf_round(x0,x1,17); tf_round(x0,x1,29); tf_round(x0,x1,16); tf_round(x0,x1,24);
    x0 += ks1; x1 += ks2 + 4u;
    tf_round(x0,x1,13); tf_round(x0,x1,15); tf_round(x0,x1,26); tf_round(x0,x1,6);
    x0 += ks2; x1 += ks0 + 5u;
    return x0 ^ x1;
}

// ---------------------------------------------------------------------------
// helpers
// ---------------------------------------------------------------------------
__device__ __forceinline__ float hif(float x) {
    return __half2float(__float2half_rn(x));
}
__device__ __forceinline__ uint packh2(float lo, float hi) {
    uint r; asm("cvt.rn.f16x2.f32 %0, %1, %2;" : "=r"(r) : "f"(hi), "f"(lo)); return r;
}

// ---------------------------------------------------------------------------
// K/V convert kernel (memory-bound, ~20us): fp32 -> fp16 hi/lo padded planes
// ---------------------------------------------------------------------------
__global__ void __launch_bounds__(256) conv_kernel(
    const float* __restrict__ K, const float* __restrict__ V)
{
    const uint u = blockIdx.x * 256u + threadIdx.x;   // 0 .. 2^20-1
    const uint row = u >> 5;
    const uint c4  = (u & 31u) << 2;
    const float4 k4 = *reinterpret_cast<const float4*>(K + (size_t)row * D_ + c4);
    const float4 v4 = *reinterpret_cast<const float4*>(V + (size_t)row * D_ + c4);

    const size_t po = (size_t)row * ROWB + (size_t)c4 * 2;
    {
        const float h0 = hif(k4.x), h1 = hif(k4.y), h2 = hif(k4.z), h3 = hif(k4.w);
        *reinterpret_cast<ull*>(gKhi + po) =
            (ull)packh2(h0, h1) | ((ull)packh2(h2, h3) << 32);
        *reinterpret_cast<ull*>(gKlo + po) =
            (ull)packh2(k4.x - h0, k4.y - h1) | ((ull)packh2(k4.z - h2, k4.w - h3) << 32);
    }
    {
        const float h0 = hif(v4.x), h1 = hif(v4.y), h2 = hif(v4.z), h3 = hif(v4.w);
        *reinterpret_cast<ull*>(gVhi + po) =
            (ull)packh2(h0, h1) | ((ull)packh2(h2, h3) << 32);
        *reinterpret_cast<ull*>(gVlo + po) =
            (ull)packh2(v4.x - h0, v4.y - h1) | ((ull)packh2(v4.z - h2, v4.w - h3) << 32);
    }
}

// ---------------------------------------------------------------------------
// mma / ldmatrix / cp.async helpers (baseline PTX)
// ---------------------------------------------------------------------------
__device__ __forceinline__ unsigned smem_u32(const void* p) {
    unsigned a;
    asm("{ .reg .u64 t; cvta.to.shared.u64 t, %1; cvt.u32.u64 %0, t; }"
        : "=r"(a) : "l"(p));
    return a;
}

__device__ __forceinline__ void mma16816(float* c, const uint* a, uint b0, uint b1) {
    asm volatile(
        "mma.sync.aligned.m16n8k16.row.col.f32.f16.f16.f32 "
        "{%0,%1,%2,%3}, {%4,%5,%6,%7}, {%8,%9}, {%0,%1,%2,%3};"
        : "+f"(c[0]), "+f"(c[1]), "+f"(c[2]), "+f"(c[3])
        : "r"(a[0]), "r"(a[1]), "r"(a[2]), "r"(a[3]), "r"(b0), "r"(b1));
}

__device__ __forceinline__ void ldsm4(uint* r, uint addr) {
    asm volatile("ldmatrix.sync.aligned.m8n8.x4.shared.b16 {%0,%1,%2,%3}, [%4];"
        : "=r"(r[0]), "=r"(r[1]), "=r"(r[2]), "=r"(r[3]) : "r"(addr));
}
__device__ __forceinline__ void ldsm4t(uint* r, uint addr) {
    asm volatile("ldmatrix.sync.aligned.m8n8.x4.trans.shared.b16 {%0,%1,%2,%3}, [%4];"
        : "=r"(r[0]), "=r"(r[1]), "=r"(r[2]), "=r"(r[3]) : "r"(addr));
}

__device__ __forceinline__ void cpasync16(uint dst, const void* src) {
    asm volatile("cp.async.cg.shared.global [%0], [%1], 16;" :: "r"(dst), "l"(src));
}
__device__ __forceinline__ void cp_commit() {
    asm volatile("cp.async.commit_group;" ::: "memory");
}
__device__ __forceinline__ void cp_wait1() {
    asm volatile("cp.async.wait_group 1;" ::: "memory");
}
__device__ __forceinline__ void cp_wait0() {
    asm volatile("cp.async.wait_group 0;" ::: "memory");
}

__device__ __forceinline__ void split_store(char* smp, int hi_off, int lo_off,
                                            int byte_off, float4 v) {
    const float h0 = hif(v.x), h1 = hif(v.y), h2 = hif(v.z), h3 = hif(v.w);
    const uint hi01 = packh2(h0, h1), hi23 = packh2(h2, h3);
    const uint lo01 = packh2(v.x - h0, v.y - h1), lo23 = packh2(v.z - h2, v.w - h3);
    *reinterpret_cast<ull*>(smp + hi_off + byte_off) = (ull)hi01 | ((ull)hi23 << 32);
    *reinterpret_cast<ull*>(smp + lo_off + byte_off) = (ull)lo01 | ((ull)lo23 << 32);
}

// merge per-lane byte into full 32-bit mask word across the 4-lane tc group
__device__ __forceinline__ uint merge4(uint m, int tc) {
    uint v = m << (8 * tc);
    v |= __shfl_xor_sync(0xffffffffu, v, 1);
    v |= __shfl_xor_sync(0xffffffffu, v, 2);
    return v;
}

// ---------------------------------------------------------------------------
// Flash attention: split-fp16 HMMA + instruction-interleaved Threefry.
// BQ=BK=128, 512 threads (16 warps). warp w: wq=w&7 (q-rows), h=w>>3 (half).
// Mask for tile kb+1 is generated inside tile kb's QK/PV mma loops
// (4 chains per QK iter, 2 per PV iter); tile 0 in a prologue.
// ---------------------------------------------------------------------------
__global__ void __launch_bounds__(512, 1) attn_kernel(
    const float* __restrict__ Q, const float* __restrict__ inv_scale,
    const float* __restrict__ p_dropout, float* __restrict__ Out)
{
    extern __shared__ char smp[];
    const uint sb = smem_u32(smp);

    const int b     = blockIdx.y;
    const int qbase = blockIdx.x * BQ;
    const int tid   = threadIdx.x;
    const int lane  = tid & 31;
    const int warp  = tid >> 5;
    const int wq    = warp & 7;
    const int h     = warp >> 3;
    const int qr    = wq * 16;
    const int g     = lane >> 2;
    const int tc    = lane & 3;

    const float kp = 1.0f - *p_dropout;
    // integer keep threshold: (bits>>9) < tint  <=>  uniform < kp   (exact)
    const uint tint = __float2uint_ru(kp * 8388608.0f);

    const float* Qb = Q + (size_t)(b * S_ + qbase) * D_;
    float* redM = (float*)(smp + REDM);
    float* redZ = (float*)(smp + REDZ);

    // ---- Q -> hi/lo fp16 planes (once) ----
    for (int t = tid; t < 128 * 32; t += 512) {
        const int r = t >> 5, c4 = (t & 31) << 2;
        split_store(smp, QHI, QLO, r * ROWB + c4 * 2,
                    *reinterpret_cast<const float4*>(Qb + r * D_ + c4));
    }

    const float rsc0 = 1.0f / inv_scale[(size_t)b * S_ + qbase + qr + g];
    const float rsc1 = 1.0f / inv_scale[(size_t)b * S_ + qbase + qr + g + 8];

    float oacc[8][4];
#pragma unroll
    for (int nt = 0; nt < 8; nt++)
#pragma unroll
        for (int j = 0; j < 4; j++) oacc[nt][j] = 0.0f;
    float m0 = -1e30f, m1 = -1e30f, z0 = 0.0f, z1 = 0.0f;

    // threefry element bases: row_elem = global_row * 2048
    const unsigned erow0 = (unsigned)(b * S_ + qbase + qr + g) * 2048u;
    const unsigned erow1 = erow0 + 8u * 2048u;

    // per-lane ldmatrix byte offsets
    const uint aoff = (uint)((qr + (lane & 15)) * HSTR + ((lane >> 4) << 3)) * 2;
    const uint boff = (uint)(((h * 64 + ((lane >> 4) << 3)) + (lane & 7)) * HSTR
                             + (((lane >> 3) & 1) << 3)) * 2;
    const uint voff = (uint)(((((lane >> 3) & 1) << 3) + (lane & 7)) * HSTR
                             + (h * 64 + ((lane >> 4) << 3))) * 2;

    // ---- prologue: mask words for tile 0 ----
    uint mw[4];
#pragma unroll
    for (int w = 0; w < 4; w++) {
        const unsigned er = (w < 2) ? erow0 : erow1;
        const unsigned base = er + (unsigned)(h * 2 + (w & 1)) * 32u + (unsigned)(8 * tc);
        uint m = 0;
#pragma unroll
        for (int e = 0; e < 8; e++)
            m |= ((tf_bits(base + (unsigned)e) >> 9) < tint ? 1u : 0u) << e;
        mw[w] = merge4(m, tc);
    }
    uint myb0 = 0, myb1 = 0, myb2 = 0, myb3 = 0;   // in-progress for next tile

    for (int kb = 0; kb < NIT; kb++) {
        const bool gen = (kb + 1 < NIT);
        // element base for next tile's words (w: 0,1 -> row0 j=0,1; 2,3 -> row1)
        const unsigned nb = (unsigned)((kb + 1) * 4 + h * 2) * 32u + (unsigned)(8 * tc);

        __syncthreads();   // (a) prior PV reads of P/V done

        // ---- cp.async K planes (group A) then V planes (group B) ----
        {
            const size_t gof = (size_t)(b * S_ + kb * BK) * ROWB;
            for (int i = tid; i < CHUNKS; i += 512) {
                const int o = i * 16;
                cpasync16(sb + KHI + o, gKhi + gof + o);
                cpasync16(sb + KLO + o, gKlo + gof + o);
            }
            cp_commit();
            for (int i = tid; i < CHUNKS; i += 512) {
                const int o = i * 16;
                cpasync16(sb + VHI + o, gVhi + gof + o);
                cpasync16(sb + VLO + o, gVlo + gof + o);
            }
            cp_commit();
        }
        cp_wait1();        // K planes landed (V still in flight)
        __syncthreads();   // (b) K visible to all warps

        // ---- S = Q K^T (3-term) + interleaved threefry chains 0..15 ----
        float sacc[8][4];
#pragma unroll
        for (int nt = 0; nt < 8; nt++)
#pragma unroll
            for (int j = 0; j < 4; j++) sacc[nt][j] = 0.0f;

#pragma unroll
        for (int ks = 0; ks < 8; ks++) {
            // 2 chains for word0 (row0,j=0) and 2 for word1 (row0,j=1):
            // chains c = 2*ks, 2*ks+1 over words c>>3
            if (gen) {
#pragma unroll
                for (int cc = 0; cc < 2; cc++) {
                    const int c = 2 * ks + cc;         // 0..15
                    const int w = c >> 3;              // 0 or 1
                    const int e = c & 7;
                    const unsigned idx = erow0 + nb + (unsigned)(w * 32) + (unsigned)e;
                    const uint keep = ((tf_bits(idx) >> 9) < tint) ? 1u : 0u;
                    if (w == 0) myb0 |= keep << e; else myb1 |= keep << e;
                }
            }
            uint ah[4], al[4];
            ldsm4(ah, sb + QHI + aoff + ks * 32);
            ldsm4(al, sb + QLO + aoff + ks * 32);
#pragma unroll
            for (int nt2 = 0; nt2 < 4; nt2++) {
                uint bh[4], bl[4];
                const uint kbo = boff + (uint)(nt2 * 16 * ROWB + ks * 32);
                ldsm4(bh, sb + KHI + kbo);
                ldsm4(bl, sb + KLO + kbo);
                mma16816(sacc[2 * nt2],     ah, bh[0], bh[1]);
                mma16816(sacc[2 * nt2],     al, bh[0], bh[1]);
                mma16816(sacc[2 * nt2],     ah, bl[0], bl[1]);
                mma16816(sacc[2 * nt2 + 1], ah, bh[2], bh[3]);
                mma16816(sacc[2 * nt2 + 1], al, bh[2], bh[3]);
                mma16816(sacc[2 * nt2 + 1], ah, bl[2], bl[3]);
            }
        }

        // ---- scale + half-local max ----
        float mx0 = -1e30f, mx1 = -1e30f;
#pragma unroll
        for (int nt = 0; nt < 8; nt++) {
            sacc[nt][0] *= rsc0; sacc[nt][1] *= rsc0;
            sacc[nt][2] *= rsc1; sacc[nt][3] *= rsc1;
            mx0 = fmaxf(mx0, fmaxf(sacc[nt][0], sacc[nt][1]));
            mx1 = fmaxf(mx1, fmaxf(sacc[nt][2], sacc[nt][3]));
        }
        mx0 = fmaxf(mx0, __shfl_xor_sync(0xffffffffu, mx0, 1));
        mx0 = fmaxf(mx0, __shfl_xor_sync(0xffffffffu, mx0, 2));
        mx1 = fmaxf(mx1, __shfl_xor_sync(0xffffffffu, mx1, 1));
        mx1 = fmaxf(mx1, __shfl_xor_sync(0xffffffffu, mx1, 2));

        if (tc == 0) {
            redM[h * 128 + qr + g]     = mx0;
            redM[h * 128 + qr + g + 8] = mx1;
        }
        __syncthreads();   // (c) max exchange; all QK reads of K done
        mx0 = fmaxf(mx0, redM[(1 - h) * 128 + qr + g]);
        mx1 = fmaxf(mx1, redM[(1 - h) * 128 + qr + g + 8]);

        const float mn0 = fmaxf(m0, mx0), mn1 = fmaxf(m1, mx1);
        const float al0 = __expf(m0 - mn0), al1 = __expf(m1 - mn1);
        m0 = mn0; m1 = mn1;

        // ---- exp + Z partial ----
        float zp0 = 0.0f, zp1 = 0.0f;
#pragma unroll
        for (int nt = 0; nt < 8; nt++) {
            sacc[nt][0] = __expf(sacc[nt][0] - mn0); zp0 += sacc[nt][0];
            sacc[nt][1] = __expf(sacc[nt][1] - mn0); zp0 += sacc[nt][1];
            sacc[nt][2] = __expf(sacc[nt][2] - mn1); zp1 += sacc[nt][2];
            sacc[nt][3] = __expf(sacc[nt][3] - mn1); zp1 += sacc[nt][3];
        }
        zp0 += __shfl_xor_sync(0xffffffffu, zp0, 1);
        zp0 += __shfl_xor_sync(0xffffffffu, zp0, 2);
        zp1 += __shfl_xor_sync(0xffffffffu, zp1, 1);
        zp1 += __shfl_xor_sync(0xffffffffu, zp1, 2);
        z0 = z0 * al0 + zp0;
        z1 = z1 * al1 + zp1;

        // ---- dropout from current-tile mask words (generated last tile) ----
#pragma unroll
        for (int nt = 0; nt < 8; nt++) {
            const uint bit = (uint)((nt & 3) * 8 + tc * 2);
            const uint ww0 = (nt >> 2) ? mw[1] : mw[0];
            const uint ww1 = (nt >> 2) ? mw[3] : mw[2];
            if (!((ww0 >> bit) & 1u))        sacc[nt][0] = 0.0f;
            if (!((ww0 >> (bit + 1)) & 1u))  sacc[nt][1] = 0.0f;
            if (!((ww1 >> bit) & 1u))        sacc[nt][2] = 0.0f;
            if (!((ww1 >> (bit + 1)) & 1u))  sacc[nt][3] = 0.0f;
        }

        // ---- write P_hi into KHI plane; rescale O partial ----
#pragma unroll
        for (int nt = 0; nt < 8; nt++) {
            const int keyc = h * 64 + (nt >> 1) * 16 + (nt & 1) * 8 + tc * 2;
            *(uint*)(smp + KHI + (qr + g) * ROWB + keyc * 2) =
                packh2(sacc[nt][0], sacc[nt][1]);
            *(uint*)(smp + KHI + (qr + g + 8) * ROWB + keyc * 2) =
                packh2(sacc[nt][2], sacc[nt][3]);
        }
#pragma unroll
        for (int nt = 0; nt < 8; nt++) {
            oacc[nt][0] *= al0; oacc[nt][1] *= al0;
            oacc[nt][2] *= al1; oacc[nt][3] *= al1;
        }
        cp_wait0();        // V planes landed
        __syncthreads();   // (d) P + V ready

        // ---- O += P_hi * (V_hi + V_lo) + interleaved threefry chains 16..31 ----
#pragma unroll
        for (int ks = 0; ks < 8; ks++) {
            if (gen) {
#pragma unroll
                for (int cc = 0; cc < 2; cc++) {
                    const int c = 16 + 2 * ks + cc;    // 16..31
                    const int w = (c >> 3) & 1;        // 0 -> word2, 1 -> word3
                    const int e = c & 7;
                    const unsigned idx = erow1 + nb + (unsigned)(w * 32) + (unsigned)e;
                    const uint keep = ((tf_bits(idx) >> 9) < tint) ? 1u : 0u;
                    if (w == 0) myb2 |= keep << e; else myb3 |= keep << e;
                }
            }
            uint ph[4];
            ldsm4(ph, sb + KHI + aoff + ks * 32);
#pragma unroll
            for (int dt2 = 0; dt2 < 4; dt2++) {
                uint vh[4], vl[4];
                const uint vbo = voff + (uint)(ks * 16 * ROWB + dt2 * 32);
                ldsm4t(vh, sb + VHI + vbo);
                ldsm4t(vl, sb + VLO + vbo);
                mma16816(oacc[2 * dt2],     ph, vh[0], vh[1]);
                mma16816(oacc[2 * dt2],     ph, vl[0], vl[1]);
                mma16816(oacc[2 * dt2 + 1], ph, vh[2], vh[3]);
                mma16816(oacc[2 * dt2 + 1], ph, vl[2], vl[3]);
            }
        }

        // ---- finalize next tile's mask words ----
        if (gen) {
            mw[0] = merge4(myb0, tc);
            mw[1] = merge4(myb1, tc);
            mw[2] = merge4(myb2, tc);
            mw[3] = merge4(myb3, tc);
            myb0 = myb1 = myb2 = myb3 = 0;
        }
    }

    // ---- epilogue: exchange Z halves, normalize, store ----
    if (tc == 0) {
        redZ[h * 128 + qr + g]     = z0;
        redZ[h * 128 + qr + g + 8] = z1;
    }
    __syncthreads();
    const float Z0 = redZ[qr + g]     + redZ[128 + qr + g];
    const float Z1 = redZ[qr + g + 8] + redZ[128 + qr + g + 8];
    const float inv0 = 1.0f / (Z0 * kp);
    const float inv1 = 1.0f / (Z1 * kp);

    float* o0 = Out + (size_t)(b * S_ + qbase + qr + g) * D_ + h * 64 + tc * 2;
    float* o1 = Out + (size_t)(b * S_ + qbase + qr + g + 8) * D_ + h * 64 + tc * 2;
#pragma unroll
    for (int nt = 0; nt < 8; nt++) {
        const int dcol = (nt >> 1) * 16 + (nt & 1) * 8;
        *reinterpret_cast<float2*>(o0 + dcol) =
            make_float2(oacc[nt][0] * inv0, oacc[nt][1] * inv0);
        *reinterpret_cast<float2*>(o1 + dcol) =
            make_float2(oacc[nt][2] * inv1, oacc[nt][3] * inv1);
    }
}

// ---------------------------------------------------------------------------
// Launch
// ---------------------------------------------------------------------------
extern "C" void kernel_launch(void* const* d_in, const int* in_sizes, int n_in,
                              void* d_out, int out_size) {
    const float* Q   = (const float*)d_in[0];
    const float* K   = (const float*)d_in[1];
    const float* V   = (const float*)d_in[2];
    const float* isf = (const float*)d_in[3];
    const float* dp  = (const float*)d_in[4];
    float* Out = (float*)d_out;

    cudaFuncSetAttribute(attn_kernel,
                         cudaFuncAttributeMaxDynamicSharedMemorySize, SMEM_BYTES);

    // 1) K/V fp32 -> fp16 hi/lo plane conversion (memory-bound, ~20us)
    conv_kernel<<<(1u << 20) / 256, 256>>>(K, V);

    // 2) flash attention with instruction-interleaved threefry mask generation
    dim3 grid(S_ / BQ, B_);
    attn_kernel<<<grid, 512, SMEM_BYTES>>>(Q, isf, dp, Out);
}

// round 17
// speedup vs baseline: 1.5172x; 1.0711x over previous
#include <cuda_runtime.h>
#include <cuda_fp16.h>
#include <cstdint>

typedef unsigned long long ull;
typedef unsigned uint;

// ---------------------------------------------------------------------------
// Problem constants
// ---------------------------------------------------------------------------
constexpr int B_ = 16, S_ = 2048, D_ = 128;
constexpr int BQ = 128, BK = 128;
constexpr int NIT = S_ / BK;        // 16
constexpr int HSTR = 136;           // halfs per smem row (272B)
constexpr int ROWB = HSTR * 2;      // 272 bytes per padded row

constexpr int PLANE = 128 * ROWB;   // 34816 B per 128-row plane
constexpr int QHI = 0;
constexpr int QLO = QHI + PLANE;
constexpr int KHI = QLO + PLANE;    // P_hi overlays after QK
constexpr int KLO = KHI + PLANE;
constexpr int VHI = KLO + PLANE;    // V hi only (V_lo dropped)
constexpr int REDM = VHI + PLANE;   // float[2][128]
constexpr int REDZ = REDM + 1024;   // float[2][128]
constexpr int SMEM_BYTES = REDZ + 1024;   // 176128

constexpr int CHUNKS = PLANE / 16;  // 2176 16B chunks per plane

// Pre-converted K/V planes in global (padded row image identical to smem)
__device__ __align__(256) char gKhi[B_ * S_ * ROWB];
__device__ __align__(256) char gKlo[B_ * S_ * ROWB];
__device__ __align__(256) char gVhi[B_ * S_ * ROWB];

// ---------------------------------------------------------------------------
// Threefry-2x32 (JAX partitionable): key=(0,42), ctr=(0,idx), draw = x0^x1
// ---------------------------------------------------------------------------
__device__ __forceinline__ void tf_round(unsigned &x0, unsigned &x1, int r) {
    x0 += x1;
    x1 = __funnelshift_l(x1, x1, r);
    x1 ^= x0;
}

__device__ __forceinline__ unsigned tf_bits(unsigned idx) {
    const unsigned ks0 = 0u, ks1 = 42u, ks2 = 0x1BD11BDAu ^ 42u;
    unsigned x0 = ks0, x1 = idx + ks1;
    tf_round(x0,x1,13); tf_round(x0,x1,15); tf_round(x0,x1,26); tf_round(x0,x1,6);
    x0 += ks1; x1 += ks2 + 1u;
    tf_round(x0,x1,17); tf_round(x0,x1,29); tf_round(x0,x1,16); tf_round(x0,x1,24);
    x0 += ks2; x1 += ks0 + 2u;
    tf_round(x0,x1,13); tf_round(x0,x1,15); tf_round(x0,x1,26); tf_round(x0,x1,6);
    x0 += ks0; x1 += ks1 + 3u;
    tf_round(x0,x1,17); tf_round(x0,x1,29); tf_round(x0,x1,16); tf_round(x0,x1,24);
    x0 += ks1; x1 += ks2 + 4u;
    tf_round(x0,x1,13); tf_round(x0,x1,15); tf_round(x0,x1,26); tf_round(x0,x1,6);
    x0 += ks2; x1 += ks0 + 5u;
    return x0 ^ x1;
}

// ---------------------------------------------------------------------------
// helpers
// ---------------------------------------------------------------------------
__device__ __forceinline__ float hif(float x) {
    return __half2float(__float2half_rn(x));
}
__device__ __forceinline__ uint packh2(float lo, float hi) {
    uint r; asm("cvt.rn.f16x2.f32 %0, %1, %2;" : "=r"(r) : "f"(hi), "f"(lo)); return r;
}

// ---------------------------------------------------------------------------
// K/V convert kernel (memory-bound): K -> fp16 hi/lo planes, V -> fp16 hi only
// ---------------------------------------------------------------------------
__global__ void __launch_bounds__(256) conv_kernel(
    const float* __restrict__ K, const float* __restrict__ V)
{
    const uint u = blockIdx.x * 256u + threadIdx.x;   // 0 .. 2^20-1
    const uint row = u >> 5;
    const uint c4  = (u & 31u) << 2;
    const float4 k4 = *reinterpret_cast<const float4*>(K + (size_t)row * D_ + c4);
    const float4 v4 = *reinterpret_cast<const float4*>(V + (size_t)row * D_ + c4);

    const size_t po = (size_t)row * ROWB + (size_t)c4 * 2;
    {
        const float h0 = hif(k4.x), h1 = hif(k4.y), h2 = hif(k4.z), h3 = hif(k4.w);
        *reinterpret_cast<ull*>(gKhi + po) =
            (ull)packh2(h0, h1) | ((ull)packh2(h2, h3) << 32);
        *reinterpret_cast<ull*>(gKlo + po) =
            (ull)packh2(k4.x - h0, k4.y - h1) | ((ull)packh2(k4.z - h2, k4.w - h3) << 32);
    }
    *reinterpret_cast<ull*>(gVhi + po) =
        (ull)packh2(v4.x, v4.y) | ((ull)packh2(v4.z, v4.w) << 32);
}

// ---------------------------------------------------------------------------
// mma / ldmatrix / cp.async helpers (baseline PTX)
// ---------------------------------------------------------------------------
__device__ __forceinline__ unsigned smem_u32(const void* p) {
    unsigned a;
    asm("{ .reg .u64 t; cvta.to.shared.u64 t, %1; cvt.u32.u64 %0, t; }"
        : "=r"(a) : "l"(p));
    return a;
}

__device__ __forceinline__ void mma16816(float* c, const uint* a, uint b0, uint b1) {
    asm volatile(
        "mma.sync.aligned.m16n8k16.row.col.f32.f16.f16.f32 "
        "{%0,%1,%2,%3}, {%4,%5,%6,%7}, {%8,%9}, {%0,%1,%2,%3};"
        : "+f"(c[0]), "+f"(c[1]), "+f"(c[2]), "+f"(c[3])
        : "r"(a[0]), "r"(a[1]), "r"(a[2]), "r"(a[3]), "r"(b0), "r"(b1));
}

__device__ __forceinline__ void ldsm4(uint* r, uint addr) {
    asm volatile("ldmatrix.sync.aligned.m8n8.x4.shared.b16 {%0,%1,%2,%3}, [%4];"
        : "=r"(r[0]), "=r"(r[1]), "=r"(r[2]), "=r"(r[3]) : "r"(addr));
}
__device__ __forceinline__ void ldsm4t(uint* r, uint addr) {
    asm volatile("ldmatrix.sync.aligned.m8n8.x4.trans.shared.b16 {%0,%1,%2,%3}, [%4];"
        : "=r"(r[0]), "=r"(r[1]), "=r"(r[2]), "=r"(r[3]) : "r"(addr));
}

__device__ __forceinline__ void cpasync16(uint dst, const void* src) {
    asm volatile("cp.async.cg.shared.global [%0], [%1], 16;" :: "r"(dst), "l"(src));
}
__device__ __forceinline__ void cp_commit() {
    asm volatile("cp.async.commit_group;" ::: "memory");
}
__device__ __forceinline__ void cp_wait1() {
    asm volatile("cp.async.wait_group 1;" ::: "memory");
}
__device__ __forceinline__ void cp_wait0() {
    asm volatile("cp.async.wait_group 0;" ::: "memory");
}

__device__ __forceinline__ void split_store(char* smp, int hi_off, int lo_off,
                                            int byte_off, float4 v) {
    const float h0 = hif(v.x), h1 = hif(v.y), h2 = hif(v.z), h3 = hif(v.w);
    const uint hi01 = packh2(h0, h1), hi23 = packh2(h2, h3);
    const uint lo01 = packh2(v.x - h0, v.y - h1), lo23 = packh2(v.z - h2, v.w - h3);
    *reinterpret_cast<ull*>(smp + hi_off + byte_off) = (ull)hi01 | ((ull)hi23 << 32);
    *reinterpret_cast<ull*>(smp + lo_off + byte_off) = (ull)lo01 | ((ull)lo23 << 32);
}

// merge per-lane byte into full 32-bit mask word across the 4-lane tc group
__device__ __forceinline__ uint merge4(uint m, int tc) {
    uint v = m << (8 * tc);
    v |= __shfl_xor_sync(0xffffffffu, v, 1);
    v |= __shfl_xor_sync(0xffffffffu, v, 2);
    return v;
}

// ---------------------------------------------------------------------------
// Flash attention: split-fp16 HMMA + instruction-interleaved Threefry.
// BQ=BK=128, 512 threads (16 warps). warp w: wq=w&7 (q-rows), h=w>>3 (half).
// QK 3-term (exact logits); PV single-term with fp16 V (rel err ~2.8e-4).
// Mask for tile kb+1 generated inside tile kb's mma loops.
// ---------------------------------------------------------------------------
__global__ void __launch_bounds__(512, 1) attn_kernel(
    const float* __restrict__ Q, const float* __restrict__ inv_scale,
    const float* __restrict__ p_dropout, float* __restrict__ Out)
{
    extern __shared__ char smp[];
    const uint sb = smem_u32(smp);

    const int b     = blockIdx.y;
    const int qbase = blockIdx.x * BQ;
    const int tid   = threadIdx.x;
    const int lane  = tid & 31;
    const int warp  = tid >> 5;
    const int wq    = warp & 7;
    const int h     = warp >> 3;
    const int qr    = wq * 16;
    const int g     = lane >> 2;
    const int tc    = lane & 3;

    const float kp = 1.0f - *p_dropout;
    const uint tint = __float2uint_ru(kp * 8388608.0f);   // exact int threshold

    const float* Qb = Q + (size_t)(b * S_ + qbase) * D_;
    float* redM = (float*)(smp + REDM);
    float* redZ = (float*)(smp + REDZ);

    // ---- Q -> hi/lo fp16 planes (once) ----
    for (int t = tid; t < 128 * 32; t += 512) {
        const int r = t >> 5, c4 = (t & 31) << 2;
        split_store(smp, QHI, QLO, r * ROWB + c4 * 2,
                    *reinterpret_cast<const float4*>(Qb + r * D_ + c4));
    }

    const float rsc0 = 1.0f / inv_scale[(size_t)b * S_ + qbase + qr + g];
    const float rsc1 = 1.0f / inv_scale[(size_t)b * S_ + qbase + qr + g + 8];

    float oacc[8][4];
#pragma unroll
    for (int nt = 0; nt < 8; nt++)
#pragma unroll
        for (int j = 0; j < 4; j++) oacc[nt][j] = 0.0f;
    float m0 = -1e30f, m1 = -1e30f, z0 = 0.0f, z1 = 0.0f;

    const unsigned erow0 = (unsigned)(b * S_ + qbase + qr + g) * 2048u;
    const unsigned erow1 = erow0 + 8u * 2048u;

    // per-lane ldmatrix byte offsets
    const uint aoff = (uint)((qr + (lane & 15)) * HSTR + ((lane >> 4) << 3)) * 2;
    const uint boff = (uint)(((h * 64 + ((lane >> 4) << 3)) + (lane & 7)) * HSTR
                             + (((lane >> 3) & 1) << 3)) * 2;
    const uint voff = (uint)(((((lane >> 3) & 1) << 3) + (lane & 7)) * HSTR
                             + (h * 64 + ((lane >> 4) << 3))) * 2;

    // ---- prologue: mask words for tile 0 ----
    uint mw[4];
#pragma unroll
    for (int w = 0; w < 4; w++) {
        const unsigned er = (w < 2) ? erow0 : erow1;
        const unsigned base = er + (unsigned)(h * 2 + (w & 1)) * 32u + (unsigned)(8 * tc);
        uint m = 0;
#pragma unroll
        for (int e = 0; e < 8; e++)
            m |= ((tf_bits(base + (unsigned)e) >> 9) < tint ? 1u : 0u) << e;
        mw[w] = merge4(m, tc);
    }
    uint myb0 = 0, myb1 = 0, myb2 = 0, myb3 = 0;

    for (int kb = 0; kb < NIT; kb++) {
        const bool gen = (kb + 1 < NIT);
        const unsigned nb = (unsigned)((kb + 1) * 4 + h * 2) * 32u + (unsigned)(8 * tc);

        __syncthreads();   // (a) prior PV reads of P/V done

        // ---- cp.async K planes (group A) then V plane (group B) ----
        {
            const size_t gof = (size_t)(b * S_ + kb * BK) * ROWB;
            for (int i = tid; i < CHUNKS; i += 512) {
                const int o = i * 16;
                cpasync16(sb + KHI + o, gKhi + gof + o);
                cpasync16(sb + KLO + o, gKlo + gof + o);
            }
            cp_commit();
            for (int i = tid; i < CHUNKS; i += 512) {
                const int o = i * 16;
                cpasync16(sb + VHI + o, gVhi + gof + o);
            }
            cp_commit();
        }
        cp_wait1();        // K planes landed (V still in flight)
        __syncthreads();   // (b) K visible to all warps

        // ---- S = Q K^T (3-term) + interleaved threefry chains 0..15 ----
        float sacc[8][4];
#pragma unroll
        for (int nt = 0; nt < 8; nt++)
#pragma unroll
            for (int j = 0; j < 4; j++) sacc[nt][j] = 0.0f;

#pragma unroll
        for (int ks = 0; ks < 8; ks++) {
            if (gen) {
#pragma unroll
                for (int cc = 0; cc < 2; cc++) {
                    const int c = 2 * ks + cc;         // 0..15
                    const int w = c >> 3;              // 0 or 1
                    const int e = c & 7;
                    const unsigned idx = erow0 + nb + (unsigned)(w * 32) + (unsigned)e;
                    const uint keep = ((tf_bits(idx) >> 9) < tint) ? 1u : 0u;
                    if (w == 0) myb0 |= keep << e; else myb1 |= keep << e;
                }
            }
            uint ah[4], al[4];
            ldsm4(ah, sb + QHI + aoff + ks * 32);
            ldsm4(al, sb + QLO + aoff + ks * 32);
#pragma unroll
            for (int nt2 = 0; nt2 < 4; nt2++) {
                uint bh[4], bl[4];
                const uint kbo = boff + (uint)(nt2 * 16 * ROWB + ks * 32);
                ldsm4(bh, sb + KHI + kbo);
                ldsm4(bl, sb + KLO + kbo);
                mma16816(sacc[2 * nt2],     ah, bh[0], bh[1]);
                mma16816(sacc[2 * nt2],     al, bh[0], bh[1]);
                mma16816(sacc[2 * nt2],     ah, bl[0], bl[1]);
                mma16816(sacc[2 * nt2 + 1], ah, bh[2], bh[3]);
                mma16816(sacc[2 * nt2 + 1], al, bh[2], bh[3]);
                mma16816(sacc[2 * nt2 + 1], ah, bl[2], bl[3]);
            }
        }

        // ---- scale + half-local max ----
        float mx0 = -1e30f, mx1 = -1e30f;
#pragma unroll
        for (int nt = 0; nt < 8; nt++) {
            sacc[nt][0] *= rsc0; sacc[nt][1] *= rsc0;
            sacc[nt][2] *= rsc1; sacc[nt][3] *= rsc1;
            mx0 = fmaxf(mx0, fmaxf(sacc[nt][0], sacc[nt][1]));
            mx1 = fmaxf(mx1, fmaxf(sacc[nt][2], sacc[nt][3]));
        }
        mx0 = fmaxf(mx0, __shfl_xor_sync(0xffffffffu, mx0, 1));
        mx0 = fmaxf(mx0, __shfl_xor_sync(0xffffffffu, mx0, 2));
        mx1 = fmaxf(mx1, __shfl_xor_sync(0xffffffffu, mx1, 1));
        mx1 = fmaxf(mx1, __shfl_xor_sync(0xffffffffu, mx1, 2));

        if (tc == 0) {
            redM[h * 128 + qr + g]     = mx0;
            redM[h * 128 + qr + g + 8] = mx1;
        }
        __syncthreads();   // (c) max exchange; all QK reads of K done
        mx0 = fmaxf(mx0, redM[(1 - h) * 128 + qr + g]);
        mx1 = fmaxf(mx1, redM[(1 - h) * 128 + qr + g + 8]);

        const float mn0 = fmaxf(m0, mx0), mn1 = fmaxf(m1, mx1);
        const float al0 = __expf(m0 - mn0), al1 = __expf(m1 - mn1);
        m0 = mn0; m1 = mn1;

        // ---- exp + Z partial ----
        float zp0 = 0.0f, zp1 = 0.0f;
#pragma unroll
        for (int nt = 0; nt < 8; nt++) {
            sacc[nt][0] = __expf(sacc[nt][0] - mn0); zp0 += sacc[nt][0];
            sacc[nt][1] = __expf(sacc[nt][1] - mn0); zp0 += sacc[nt][1];
            sacc[nt][2] = __expf(sacc[nt][2] - mn1); zp1 += sacc[nt][2];
            sacc[nt][3] = __expf(sacc[nt][3] - mn1); zp1 += sacc[nt][3];
        }
        zp0 += __shfl_xor_sync(0xffffffffu, zp0, 1);
        zp0 += __shfl_xor_sync(0xffffffffu, zp0, 2);
        zp1 += __shfl_xor_sync(0xffffffffu, zp1, 1);
        zp1 += __shfl_xor_sync(0xffffffffu, zp1, 2);
        z0 = z0 * al0 + zp0;
        z1 = z1 * al1 + zp1;

        // ---- dropout from current-tile mask words ----
#pragma unroll
        for (int nt = 0; nt < 8; nt++) {
            const uint bit = (uint)((nt & 3) * 8 + tc * 2);
            const uint ww0 = (nt >> 2) ? mw[1] : mw[0];
            const uint ww1 = (nt >> 2) ? mw[3] : mw[2];
            if (!((ww0 >> bit) & 1u))        sacc[nt][0] = 0.0f;
            if (!((ww0 >> (bit + 1)) & 1u))  sacc[nt][1] = 0.0f;
            if (!((ww1 >> bit) & 1u))        sacc[nt][2] = 0.0f;
            if (!((ww1 >> (bit + 1)) & 1u))  sacc[nt][3] = 0.0f;
        }

        // ---- write P_hi into KHI plane; rescale O partial ----
#pragma unroll
        for (int nt = 0; nt < 8; nt++) {
            const int keyc = h * 64 + (nt >> 1) * 16 + (nt & 1) * 8 + tc * 2;
            *(uint*)(smp + KHI + (qr + g) * ROWB + keyc * 2) =
                packh2(sacc[nt][0], sacc[nt][1]);
            *(uint*)(smp + KHI + (qr + g + 8) * ROWB + keyc * 2) =
                packh2(sacc[nt][2], sacc[nt][3]);
        }
#pragma unroll
        for (int nt = 0; nt < 8; nt++) {
            oacc[nt][0] *= al0; oacc[nt][1] *= al0;
            oacc[nt][2] *= al1; oacc[nt][3] *= al1;
        }
        cp_wait0();        // V plane landed
        __syncthreads();   // (d) P + V ready

        // ---- O += P_hi * V_hi + interleaved threefry chains 16..31 ----
#pragma unroll
        for (int ks = 0; ks < 8; ks++) {
            if (gen) {
#pragma unroll
                for (int cc = 0; cc < 2; cc++) {
                    const int c = 16 + 2 * ks + cc;    // 16..31
                    const int w = (c >> 3) & 1;        // 0 -> word2, 1 -> word3
                    const int e = c & 7;
                    const unsigned idx = erow1 + nb + (unsigned)(w * 32) + (unsigned)e;
                    const uint keep = ((tf_bits(idx) >> 9) < tint) ? 1u : 0u;
                    if (w == 0) myb2 |= keep << e; else myb3 |= keep << e;
                }
            }
            uint ph[4];
            ldsm4(ph, sb + KHI + aoff + ks * 32);
#pragma unroll
            for (int dt2 = 0; dt2 < 4; dt2++) {
                uint vh[4];
                const uint vbo = voff + (uint)(ks * 16 * ROWB + dt2 * 32);
                ldsm4t(vh, sb + VHI + vbo);
                mma16816(oacc[2 * dt2],     ph, vh[0], vh[1]);
                mma16816(oacc[2 * dt2 + 1], ph, vh[2], vh[3]);
            }
        }

        // ---- finalize next tile's mask words ----
        if (gen) {
            mw[0] = merge4(myb0, tc);
            mw[1] = merge4(myb1, tc);
            mw[2] = merge4(myb2, tc);
            mw[3] = merge4(myb3, tc);
            myb0 = myb1 = myb2 = myb3 = 0;
        }
    }

    // ---- epilogue: exchange Z halves, normalize, store ----
    if (tc == 0) {
        redZ[h * 128 + qr + g]     = z0;
        redZ[h * 128 + qr + g + 8] = z1;
    }
    __syncthreads();
    const float Z0 = redZ[qr + g]     + redZ[128 + qr + g];
    const float Z1 = redZ[qr + g + 8] + redZ[128 + qr + g + 8];
    const float inv0 = 1.0f / (Z0 * kp);
    const float inv1 = 1.0f / (Z1 * kp);

    float* o0 = Out + (size_t)(b * S_ + qbase + qr + g) * D_ + h * 64 + tc * 2;
    float* o1 = Out + (size_t)(b * S_ + qbase + qr + g + 8) * D_ + h * 64 + tc * 2;
#pragma unroll
    for (int nt = 0; nt < 8; nt++) {
        const int dcol = (nt >> 1) * 16 + (nt & 1) * 8;
        *reinterpret_cast<float2*>(o0 + dcol) =
            make_float2(oacc[nt][0] * inv0, oacc[nt][1] * inv0);
        *reinterpret_cast<float2*>(o1 + dcol) =
            make_float2(oacc[nt][2] * inv1, oacc[nt][3] * inv1);
    }
}

// ---------------------------------------------------------------------------
// Launch
// ---------------------------------------------------------------------------
extern "C" void kernel_launch(void* const* d_in, const int* in_sizes, int n_in,
                              void* d_out, int out_size) {
    const float* Q   = (const float*)d_in[0];
    const float* K   = (const float*)d_in[1];
    const float* V   = (const float*)d_in[2];
    const float* isf = (const float*)d_in[3];
    const float* dp  = (const float*)d_in[4];
    float* Out = (float*)d_out;

    cudaFuncSetAttribute(attn_kernel,
                         cudaFuncAttributeMaxDynamicSharedMemorySize, SMEM_BYTES);

    // 1) K -> fp16 hi/lo planes, V -> fp16 hi plane (memory-bound, ~15us)
    conv_kernel<<<(1u << 20) / 256, 256>>>(K, V);

    // 2) flash attention with instruction-interleaved threefry mask generation
    dim3 grid(S_ / BQ, B_);
    attn_kernel<<<grid, 512, SMEM_BYTES>>>(Q, isf, dp, Out);
}